// round 3
// baseline (speedup 1.0000x reference)
#include <cuda_runtime.h>

#define N_NODES 100000
#define N_EDGES 1600000
#define DIM 128
#define EDIM 16
#define NBLK 98           // ceil(100000/1024)

// ---------------- static scratch (no allocations allowed) ----------------
__device__ __align__(16) float g_h[N_NODES * DIM];    // node features between layers
__device__ __align__(16) float g_gl[N_NODES * DIM];   // x @ Wl + bl
__device__ __align__(16) float g_gr[N_NODES * DIM];   // x @ Wr + br
__device__ int   g_cnt[N_NODES];
__device__ int   g_off[N_NODES + 1];
__device__ int   g_cursor[N_NODES];
__device__ int   g_bsum[128];
__device__ __align__(16) int2 g_einfo[N_EDGES];       // (src, edge_id) sorted by dst
__device__ float g_stats[2 * DIM];                    // sum | sumsq
__device__ float g_bnp[2 * DIM];                      // scale | shift

// ---------------- CSR build ----------------
__global__ void k_zero(int* __restrict__ cnt, float* __restrict__ stats) {
    int i = blockIdx.x * blockDim.x + threadIdx.x;
    if (i < N_NODES) cnt[i] = 0;
    if (i < 2 * DIM) stats[i] = 0.f;
}

// edge_index is INT32 (JAX silently downcasts int64 without x64 enabled).
__global__ void k_hist(const int* __restrict__ ei, int* __restrict__ cnt) {
    int e = blockIdx.x * blockDim.x + threadIdx.x;
    if (e < N_EDGES) {
        int dst = ei[N_EDGES + e];
        atomicAdd(&cnt[dst], 1);
    }
}

__global__ void k_scan1(const int* __restrict__ cnt, int* __restrict__ off,
                        int* __restrict__ bsum) {
    __shared__ int s[1024];
    int tid = threadIdx.x;
    int i = blockIdx.x * 1024 + tid;
    int v = (i < N_NODES) ? cnt[i] : 0;
    s[tid] = v; __syncthreads();
    for (int d = 1; d < 1024; d <<= 1) {
        int t = (tid >= d) ? s[tid - d] : 0;
        __syncthreads();
        s[tid] += t;
        __syncthreads();
    }
    if (i < N_NODES) off[i] = s[tid] - v;   // exclusive within block
    if (tid == 1023) bsum[blockIdx.x] = s[1023];
}

__global__ void k_scan2(int* __restrict__ bsum) {
    __shared__ int s[128];
    int tid = threadIdx.x;
    int v = (tid < NBLK) ? bsum[tid] : 0;
    s[tid] = v; __syncthreads();
    for (int d = 1; d < 128; d <<= 1) {
        int t = (tid >= d) ? s[tid - d] : 0;
        __syncthreads();
        s[tid] += t;
        __syncthreads();
    }
    if (tid < NBLK) bsum[tid] = s[tid] - v;
}

__global__ void k_scan3(int* __restrict__ off, const int* __restrict__ bsum,
                        int* __restrict__ cursor) {
    int i = blockIdx.x * blockDim.x + threadIdx.x;
    if (i < N_NODES) {
        int o = off[i] + bsum[i >> 10];
        off[i] = o;
        cursor[i] = o;
    }
    if (i == 0) off[N_NODES] = N_EDGES;
}

__global__ void k_scatter(const int* __restrict__ ei, int* __restrict__ cursor,
                          int2* __restrict__ einfo) {
    int e = blockIdx.x * blockDim.x + threadIdx.x;
    if (e < N_EDGES) {
        int src = ei[e];
        int dst = ei[N_EDGES + e];
        int pos = atomicAdd(&cursor[dst], 1);
        einfo[pos] = make_int2(src, e);
    }
}

// ---------------- dual node GEMM: gl = f(h)@Wl+bl, gr = f(h)@Wr+br ----------------
// 128 threads, 16 nodes per block. f = BN-apply + leakyReLU(0.02) (skipped layer 0).
__global__ __launch_bounds__(128) void k_gemm_dual(
    const float* __restrict__ h, int applyBN, const float* __restrict__ bnp,
    const float* __restrict__ Wl, const float* __restrict__ bl,
    const float* __restrict__ Wr, const float* __restrict__ br,
    float* __restrict__ gl, float* __restrict__ gr)
{
    __shared__ float sx[16 * DIM];
    __shared__ float sSc[DIM], sSh[DIM];
    int tid = threadIdx.x;
    sSc[tid] = bnp[tid];
    sSh[tid] = bnp[DIM + tid];
    __syncthreads();
    int n0 = blockIdx.x * 16;
#pragma unroll
    for (int it = 0; it < 16; it++) {
        int k = tid;
        int n = n0 + it;
        float v = (n < N_NODES) ? h[(size_t)n * DIM + k] : 0.0f;
        if (applyBN) {
            v = v * sSc[k] + sSh[k];
            v = v > 0.f ? v : 0.02f * v;
        }
        sx[it * DIM + k] = v;
    }
    __syncthreads();
    int j = tid;
    float accl[16], accr[16];
#pragma unroll
    for (int nn = 0; nn < 16; nn++) { accl[nn] = 0.f; accr[nn] = 0.f; }
#pragma unroll 4
    for (int k = 0; k < 128; k++) {
        float wl = Wl[k * DIM + j];
        float wr = Wr[k * DIM + j];
#pragma unroll
        for (int nn = 0; nn < 16; nn++) {
            float xv = sx[nn * DIM + k];
            accl[nn] = fmaf(xv, wl, accl[nn]);
            accr[nn] = fmaf(xv, wr, accr[nn]);
        }
    }
    float blv = bl[j], brv = br[j];
#pragma unroll
    for (int nn = 0; nn < 16; nn++) {
        int n = n0 + nn;
        if (n < N_NODES) {
            gl[(size_t)n * DIM + j] = accl[nn] + blv;
            gr[(size_t)n * DIM + j] = accr[nn] + brv;
        }
    }
}

// ---------------- final projection: out = BN/lrelu(h) @ Wf + bf ----------------
__global__ __launch_bounds__(128) void k_gemm_final(
    const float* __restrict__ h, const float* __restrict__ bnp,
    const float* __restrict__ Wf, const float* __restrict__ bf,
    float* __restrict__ out)
{
    __shared__ float sx[16 * DIM];
    __shared__ float sSc[DIM], sSh[DIM];
    int tid = threadIdx.x;
    sSc[tid] = bnp[tid];
    sSh[tid] = bnp[DIM + tid];
    __syncthreads();
    int n0 = blockIdx.x * 16;
#pragma unroll
    for (int it = 0; it < 16; it++) {
        int k = tid;
        int n = n0 + it;
        float v = (n < N_NODES) ? h[(size_t)n * DIM + k] : 0.0f;
        v = v * sSc[k] + sSh[k];
        v = v > 0.f ? v : 0.02f * v;
        sx[it * DIM + k] = v;
    }
    __syncthreads();
    int j = tid;
    float acc[16];
#pragma unroll
    for (int nn = 0; nn < 16; nn++) acc[nn] = 0.f;
#pragma unroll 4
    for (int k = 0; k < 128; k++) {
        float wf = Wf[k * DIM + j];
#pragma unroll
        for (int nn = 0; nn < 16; nn++)
            acc[nn] = fmaf(sx[nn * DIM + k], wf, acc[nn]);
    }
    float bfv = bf[j];
#pragma unroll
    for (int nn = 0; nn < 16; nn++) {
        int n = n0 + nn;
        if (n < N_NODES) out[(size_t)n * DIM + j] = acc[nn] + bfv;
    }
}

// ---------------- GATv2 aggregation: one warp per destination node ----------------
// Lane owns channels j = lane*4 .. lane*4+3 (head = lane>>3, 8 lanes per head).
// Softmax without max-subtraction (logits O(1) by construction; exact in math).
__global__ __launch_bounds__(256) void k_aggregate(
    const int* __restrict__ off, const int2* __restrict__ einfo,
    const float* __restrict__ gl, const float* __restrict__ gr,
    const float* __restrict__ We, const float* __restrict__ att,
    const float* __restrict__ bias, const float* __restrict__ EA,
    float* __restrict__ hout, float* __restrict__ stats)
{
    __shared__ float sS[8 * DIM];
    __shared__ float sQ[8 * DIM];
    int tid = threadIdx.x;
    int lane = tid & 31;
    int wrp = tid >> 5;
    int n = blockIdx.x * 8 + wrp;

    // We columns for this lane's 4 channels, held in registers (16 x float4)
    float4 we[16];
#pragma unroll
    for (int kk = 0; kk < 16; kk++)
        we[kk] = *(const float4*)(We + kk * DIM + lane * 4);

    float o0 = 0.f, o1 = 0.f, o2 = 0.f, o3 = 0.f;
    int jb = lane * 4;
    if (n < N_NODES) {
        float4 grn = *(const float4*)(gr + (size_t)n * DIM + jb);
        float4 a4  = *(const float4*)(att + jb);
        float acc0 = 0.f, acc1 = 0.f, acc2 = 0.f, acc3 = 0.f, den = 0.f;
        int beg = off[n], end = off[n + 1];
        for (int p = beg; p < end; p++) {
            int2 se = einfo[p];
            int s = se.x, eid = se.y;
            float eav = 0.f;
            if (lane < 16) eav = EA[(size_t)eid * EDIM + lane];
            float4 gls = *(const float4*)(gl + (size_t)s * DIM + jb);
            float e0 = gls.x + grn.x;
            float e1 = gls.y + grn.y;
            float e2 = gls.z + grn.z;
            float e3 = gls.w + grn.w;
#pragma unroll
            for (int kk = 0; kk < 16; kk++) {
                float b = __shfl_sync(0xffffffffu, eav, kk);
                e0 = fmaf(b, we[kk].x, e0);
                e1 = fmaf(b, we[kk].y, e1);
                e2 = fmaf(b, we[kk].z, e2);
                e3 = fmaf(b, we[kk].w, e3);
            }
            // GATv2 leaky relu, slope 0.2
            e0 = e0 > 0.f ? e0 : 0.2f * e0;
            e1 = e1 > 0.f ? e1 : 0.2f * e1;
            e2 = e2 > 0.f ? e2 : 0.2f * e2;
            e3 = e3 > 0.f ? e3 : 0.2f * e3;
            // per-head dot with att: reduce within the 8-lane head group
            float t = e0 * a4.x + e1 * a4.y + e2 * a4.z + e3 * a4.w;
            t += __shfl_xor_sync(0xffffffffu, t, 1);
            t += __shfl_xor_sync(0xffffffffu, t, 2);
            t += __shfl_xor_sync(0xffffffffu, t, 4);
            float w = __expf(t);
            den += w;
            acc0 = fmaf(w, gls.x, acc0);
            acc1 = fmaf(w, gls.y, acc1);
            acc2 = fmaf(w, gls.z, acc2);
            acc3 = fmaf(w, gls.w, acc3);
        }
        float rden = 1.0f / (den + 1e-16f);
        o0 = acc0 * rden + bias[jb + 0];
        o1 = acc1 * rden + bias[jb + 1];
        o2 = acc2 * rden + bias[jb + 2];
        o3 = acc3 * rden + bias[jb + 3];
        *(float4*)(hout + (size_t)n * DIM + jb) = make_float4(o0, o1, o2, o3);
    }
    // BN partial sums: per-warp disjoint smem slices, no smem atomics
    int base = wrp * DIM + jb;
    sS[base + 0] = o0;  sQ[base + 0] = o0 * o0;
    sS[base + 1] = o1;  sQ[base + 1] = o1 * o1;
    sS[base + 2] = o2;  sQ[base + 2] = o2 * o2;
    sS[base + 3] = o3;  sQ[base + 3] = o3 * o3;
    __syncthreads();
    if (tid < DIM) {
        float s = 0.f, q = 0.f;
#pragma unroll
        for (int w = 0; w < 8; w++) {
            s += sS[w * DIM + tid];
            q += sQ[w * DIM + tid];
        }
        atomicAdd(&stats[tid], s);
        atomicAdd(&stats[DIM + tid], q);
    }
}

// ---------------- BN stats finalize (and reset accumulators) ----------------
__global__ void k_bn_finalize(float* __restrict__ stats,
                              const float* __restrict__ gamma,
                              const float* __restrict__ beta,
                              float* __restrict__ bnp)
{
    int j = threadIdx.x;
    float inv_n = 1.0f / (float)N_NODES;
    float mu = stats[j] * inv_n;
    float var = stats[DIM + j] * inv_n - mu * mu;
    float rs = rsqrtf(var + 1e-5f);
    float sc = rs * gamma[j];
    bnp[j] = sc;
    bnp[DIM + j] = beta[j] - mu * sc;
    stats[j] = 0.f;
    stats[DIM + j] = 0.f;
}

// ---------------- launch ----------------
extern "C" void kernel_launch(void* const* d_in, const int* in_sizes, int n_in,
                              void* d_out, int out_size)
{
    const float* x    = (const float*)d_in[0];
    const int*   ei   = (const int*)d_in[1];     // int32! (JAX x64-disabled downcast)
    const float* ea   = (const float*)d_in[2];
    const float* Wl   = (const float*)d_in[3];
    const float* bl   = (const float*)d_in[4];
    const float* Wr   = (const float*)d_in[5];
    const float* br   = (const float*)d_in[6];
    const float* We   = (const float*)d_in[7];
    const float* att  = (const float*)d_in[8];
    const float* bias = (const float*)d_in[9];
    const float* gamma= (const float*)d_in[10];
    const float* beta = (const float*)d_in[11];
    const float* Wf   = (const float*)d_in[12];
    const float* bf   = (const float*)d_in[13];
    float* out = (float*)d_out;

    float *p_h, *p_gl, *p_gr, *p_stats, *p_bnp;
    int *p_cnt, *p_off, *p_cur, *p_bsum;
    int2 *p_einfo;
    cudaGetSymbolAddress((void**)&p_h,     g_h);
    cudaGetSymbolAddress((void**)&p_gl,    g_gl);
    cudaGetSymbolAddress((void**)&p_gr,    g_gr);
    cudaGetSymbolAddress((void**)&p_stats, g_stats);
    cudaGetSymbolAddress((void**)&p_bnp,   g_bnp);
    cudaGetSymbolAddress((void**)&p_cnt,   g_cnt);
    cudaGetSymbolAddress((void**)&p_off,   g_off);
    cudaGetSymbolAddress((void**)&p_cur,   g_cursor);
    cudaGetSymbolAddress((void**)&p_bsum,  g_bsum);
    cudaGetSymbolAddress((void**)&p_einfo, g_einfo);

    // CSR build (dst-sorted edge list) + zero BN accumulators
    k_zero<<<(N_NODES + 255) / 256, 256>>>(p_cnt, p_stats);
    k_hist<<<(N_EDGES + 255) / 256, 256>>>(ei, p_cnt);
    k_scan1<<<NBLK, 1024>>>(p_cnt, p_off, p_bsum);
    k_scan2<<<1, 128>>>(p_bsum);
    k_scan3<<<(N_NODES + 255) / 256, 256>>>(p_off, p_bsum, p_cur);
    k_scatter<<<(N_EDGES + 255) / 256, 256>>>(ei, p_cur, p_einfo);

    int gemm_blocks = (N_NODES + 15) / 16;   // 6250
    int agg_blocks  = (N_NODES + 7) / 8;     // 12500

    for (int L = 0; L < 3; L++) {
        const float* hin = (L == 0) ? x : p_h;
        k_gemm_dual<<<gemm_blocks, 128>>>(hin, (L > 0) ? 1 : 0, p_bnp,
                                          Wl + L * DIM * DIM, bl + L * DIM,
                                          Wr + L * DIM * DIM, br + L * DIM,
                                          p_gl, p_gr);
        k_aggregate<<<agg_blocks, 256>>>(p_off, p_einfo, p_gl, p_gr,
                                         We + L * EDIM * DIM, att + L * DIM,
                                         bias + L * DIM, ea, p_h, p_stats);
        k_bn_finalize<<<1, 128>>>(p_stats, gamma + L * DIM, beta + L * DIM, p_bnp);
    }
    k_gemm_final<<<gemm_blocks, 128>>>(p_h, p_bnp, Wf, bf, out);
}

// round 4
// speedup vs baseline: 1.2499x; 1.2499x over previous
#include <cuda_runtime.h>

#define N_NODES 100000
#define N_EDGES 1600000
#define DIM 128
#define EDIM 16
#define NBLK 98           // ceil(100000/1024)

typedef unsigned long long u64;

// f32x2 packed math (sm_103a; ptxas never auto-fuses these)
#define FMA2(d, a, b, c) asm("fma.rn.f32x2 %0, %1, %2, %3;" : "=l"(d) : "l"(a), "l"(b), "l"(c))
#define ADD2(d, a, b)    asm("add.rn.f32x2 %0, %1, %2;"     : "=l"(d) : "l"(a), "l"(b))
#define PACK2(d, lo, hi) asm("mov.b64 %0, {%1, %2};" : "=l"(d) : "r"(__float_as_uint(lo)), "r"(__float_as_uint(hi)))
#define UNPK2(lo, hi, v) do { unsigned _ulo, _uhi; asm("mov.b64 {%0, %1}, %2;" : "=r"(_ulo), "=r"(_uhi) : "l"(v)); lo = __uint_as_float(_ulo); hi = __uint_as_float(_uhi); } while (0)

// ---------------- static scratch (no allocations allowed) ----------------
__device__ __align__(16) float g_h[N_NODES * DIM];    // node features between layers
__device__ __align__(16) float g_gl[N_NODES * DIM];   // x @ Wl + bl
__device__ __align__(16) float g_gr[N_NODES * DIM];   // x @ Wr + br
__device__ int   g_cnt[N_NODES];
__device__ int   g_off[N_NODES + 1];
__device__ int   g_cursor[N_NODES];
__device__ int   g_bsum[128];
__device__ __align__(16) int2 g_einfo[N_EDGES];       // (src, edge_id) sorted by dst
__device__ float g_stats[2 * DIM];                    // sum | sumsq
__device__ float g_bnp[2 * DIM];                      // scale | shift

// ---------------- CSR build ----------------
__global__ void k_zero(int* __restrict__ cnt, float* __restrict__ stats) {
    int i = blockIdx.x * blockDim.x + threadIdx.x;
    if (i < N_NODES) cnt[i] = 0;
    if (i < 2 * DIM) stats[i] = 0.f;
}

// edge_index is INT32 (JAX x64-disabled downcast)
__global__ void k_hist(const int* __restrict__ ei, int* __restrict__ cnt) {
    int e = blockIdx.x * blockDim.x + threadIdx.x;
    if (e < N_EDGES) atomicAdd(&cnt[ei[N_EDGES + e]], 1);
}

__global__ void k_scan1(const int* __restrict__ cnt, int* __restrict__ off,
                        int* __restrict__ bsum) {
    __shared__ int s[1024];
    int tid = threadIdx.x;
    int i = blockIdx.x * 1024 + tid;
    int v = (i < N_NODES) ? cnt[i] : 0;
    s[tid] = v; __syncthreads();
    for (int d = 1; d < 1024; d <<= 1) {
        int t = (tid >= d) ? s[tid - d] : 0;
        __syncthreads();
        s[tid] += t;
        __syncthreads();
    }
    if (i < N_NODES) off[i] = s[tid] - v;   // exclusive within block
    if (tid == 1023) bsum[blockIdx.x] = s[1023];
}

// fused block-sum prefix + offset fixup + cursor init (one launch)
__global__ void k_scan23(int* __restrict__ off, const int* __restrict__ bsum,
                         int* __restrict__ cursor) {
    __shared__ int sp[NBLK];
    int tid = threadIdx.x;
    if (tid == 0) {
        int acc = 0;
        for (int b = 0; b < NBLK; b++) { sp[b] = acc; acc += bsum[b]; }
    }
    __syncthreads();
    int i = blockIdx.x * blockDim.x + tid;
    if (i < N_NODES) {
        int o = off[i] + sp[i >> 10];
        off[i] = o;
        cursor[i] = o;
    }
    if (i == 0) off[N_NODES] = N_EDGES;
}

__global__ void k_scatter(const int* __restrict__ ei, int* __restrict__ cursor,
                          int2* __restrict__ einfo) {
    int e = blockIdx.x * blockDim.x + threadIdx.x;
    if (e < N_EDGES) {
        int src = ei[e];
        int dst = ei[N_EDGES + e];
        int pos = atomicAdd(&cursor[dst], 1);
        einfo[pos] = make_int2(src, e);
    }
}

// ---------------- dual node GEMM (f32x2): gl = f(h)@Wl+bl, gr = f(h)@Wr+br ----
// 128 threads, 16 nodes per block. f = BN-apply + leakyReLU(0.02) (skipped L0).
// sx stored transposed [k][nn] with stride 20 floats (80B: 16B-aligned rows).
#define SXS 20
__global__ __launch_bounds__(128) void k_gemm_dual(
    const float* __restrict__ h, int applyBN, const float* __restrict__ bnp,
    const float* __restrict__ Wl, const float* __restrict__ bl,
    const float* __restrict__ Wr, const float* __restrict__ br,
    float* __restrict__ gl, float* __restrict__ gr)
{
    __shared__ __align__(16) float sx[128 * SXS];
    __shared__ float sSc[DIM], sSh[DIM];
    int tid = threadIdx.x;
    sSc[tid] = bnp[tid];
    sSh[tid] = bnp[DIM + tid];
    __syncthreads();
    int n0 = blockIdx.x * 16;
    {
        int k = tid;
        float sc = sSc[k], sh = sSh[k];
#pragma unroll
        for (int it = 0; it < 16; it++) {
            float v = h[(size_t)(n0 + it) * DIM + k];
            if (applyBN) {
                v = v * sc + sh;
                v = v > 0.f ? v : 0.02f * v;
            }
            sx[k * SXS + it] = v;
        }
    }
    __syncthreads();
    int j = tid;
    u64 accl[8], accr[8];
    u64 zz; PACK2(zz, 0.f, 0.f);
#pragma unroll
    for (int p = 0; p < 8; p++) { accl[p] = zz; accr[p] = zz; }
#pragma unroll 4
    for (int k = 0; k < 128; k++) {
        float wl = Wl[k * DIM + j];
        float wr = Wr[k * DIM + j];
        u64 wl2, wr2;
        PACK2(wl2, wl, wl);
        PACK2(wr2, wr, wr);
        const u64* xp = (const u64*)(sx + k * SXS);
#pragma unroll
        for (int p = 0; p < 8; p++) {
            u64 xv = xp[p];
            FMA2(accl[p], xv, wl2, accl[p]);
            FMA2(accr[p], xv, wr2, accr[p]);
        }
    }
    float blv = bl[j], brv = br[j];
#pragma unroll
    for (int p = 0; p < 8; p++) {
        float l0, l1, r0, r1;
        UNPK2(l0, l1, accl[p]);
        UNPK2(r0, r1, accr[p]);
        size_t b0 = (size_t)(n0 + 2 * p) * DIM + j;
        gl[b0] = l0 + blv;        gr[b0] = r0 + brv;
        gl[b0 + DIM] = l1 + blv;  gr[b0 + DIM] = r1 + brv;
    }
}

// ---------------- final projection (f32x2): out = BN/lrelu(h) @ Wf + bf -------
__global__ __launch_bounds__(128) void k_gemm_final(
    const float* __restrict__ h, const float* __restrict__ bnp,
    const float* __restrict__ Wf, const float* __restrict__ bf,
    float* __restrict__ out)
{
    __shared__ __align__(16) float sx[128 * SXS];
    __shared__ float sSc[DIM], sSh[DIM];
    int tid = threadIdx.x;
    sSc[tid] = bnp[tid];
    sSh[tid] = bnp[DIM + tid];
    __syncthreads();
    int n0 = blockIdx.x * 16;
    {
        int k = tid;
        float sc = sSc[k], sh = sSh[k];
#pragma unroll
        for (int it = 0; it < 16; it++) {
            float v = h[(size_t)(n0 + it) * DIM + k];
            v = v * sc + sh;
            v = v > 0.f ? v : 0.02f * v;
            sx[k * SXS + it] = v;
        }
    }
    __syncthreads();
    int j = tid;
    u64 acc[8];
    u64 zz; PACK2(zz, 0.f, 0.f);
#pragma unroll
    for (int p = 0; p < 8; p++) acc[p] = zz;
#pragma unroll 4
    for (int k = 0; k < 128; k++) {
        float wf = Wf[k * DIM + j];
        u64 wf2; PACK2(wf2, wf, wf);
        const u64* xp = (const u64*)(sx + k * SXS);
#pragma unroll
        for (int p = 0; p < 8; p++)
            FMA2(acc[p], xp[p], wf2, acc[p]);
    }
    float bfv = bf[j];
#pragma unroll
    for (int p = 0; p < 8; p++) {
        float o0, o1;
        UNPK2(o0, o1, acc[p]);
        size_t b0 = (size_t)(n0 + 2 * p) * DIM + j;
        out[b0] = o0 + bfv;
        out[b0 + DIM] = o1 + bfv;
    }
}

// ---------------- GATv2 aggregation: one warp per destination node ------------
// Lane owns channels jb..jb+3 (jb = lane*4; head = lane>>3, 8 lanes per head).
// edge_attr row loaded uniformly by all lanes (L1 broadcast) - no bcast shuffles.
// Edge transform + accumulate in packed f32x2.
__global__ __launch_bounds__(256) void k_aggregate(
    const int* __restrict__ off, const int2* __restrict__ einfo,
    const float* __restrict__ gl, const float* __restrict__ gr,
    const float* __restrict__ We, const float* __restrict__ att,
    const float* __restrict__ bias, const float* __restrict__ EA,
    float* __restrict__ hout, float* __restrict__ stats)
{
    __shared__ float sS[8 * DIM];
    __shared__ float sQ[8 * DIM];
    int tid = threadIdx.x;
    int lane = tid & 31;
    int wrp = tid >> 5;
    int n = blockIdx.x * 8 + wrp;
    int jb = lane * 4;

    // We columns for this lane's 4 channels as f32x2 pairs (16 x 2 u64)
    u64 we01[16], we23[16];
#pragma unroll
    for (int kk = 0; kk < 16; kk++) {
        ulonglong2 w = *(const ulonglong2*)(We + kk * DIM + jb);
        we01[kk] = w.x; we23[kk] = w.y;
    }

    float o0 = 0.f, o1 = 0.f, o2 = 0.f, o3 = 0.f;
    if (n < N_NODES) {
        ulonglong2 grv = *(const ulonglong2*)(gr + (size_t)n * DIM + jb);
        u64 gr01 = grv.x, gr23 = grv.y;
        float4 a4 = *(const float4*)(att + jb);
        u64 acc01, acc23;
        PACK2(acc01, 0.f, 0.f);
        acc23 = acc01;
        float den = 0.f;
        int beg = off[n], end = off[n + 1];
        for (int p = beg; p < end; p++) {
            int2 se = einfo[p];
            int s = se.x, eid = se.y;
            // uniform loads of the 64B edge_attr row (warp broadcast from L1)
            const float4* eap = (const float4*)(EA + (size_t)eid * EDIM);
            float4 ea0 = eap[0], ea1 = eap[1], ea2 = eap[2], ea3 = eap[3];
            ulonglong2 glv = *(const ulonglong2*)(gl + (size_t)s * DIM + jb);
            u64 g01 = glv.x, g23 = glv.y;
            u64 e01, e23;
            ADD2(e01, g01, gr01);
            ADD2(e23, g23, gr23);
            float eav[16] = {ea0.x, ea0.y, ea0.z, ea0.w, ea1.x, ea1.y, ea1.z, ea1.w,
                             ea2.x, ea2.y, ea2.z, ea2.w, ea3.x, ea3.y, ea3.z, ea3.w};
#pragma unroll
            for (int kk = 0; kk < 16; kk++) {
                u64 bb; PACK2(bb, eav[kk], eav[kk]);
                FMA2(e01, bb, we01[kk], e01);
                FMA2(e23, bb, we23[kk], e23);
            }
            float e0, e1, e2, e3;
            UNPK2(e0, e1, e01);
            UNPK2(e2, e3, e23);
            e0 = e0 > 0.f ? e0 : 0.2f * e0;   // GATv2 leaky relu 0.2
            e1 = e1 > 0.f ? e1 : 0.2f * e1;
            e2 = e2 > 0.f ? e2 : 0.2f * e2;
            e3 = e3 > 0.f ? e3 : 0.2f * e3;
            float t = e0 * a4.x;
            t = fmaf(e1, a4.y, t);
            t = fmaf(e2, a4.z, t);
            t = fmaf(e3, a4.w, t);
            t += __shfl_xor_sync(0xffffffffu, t, 1);
            t += __shfl_xor_sync(0xffffffffu, t, 2);
            t += __shfl_xor_sync(0xffffffffu, t, 4);
            float w = __expf(t);
            den += w;
            u64 ww; PACK2(ww, w, w);
            FMA2(acc01, ww, g01, acc01);
            FMA2(acc23, ww, g23, acc23);
        }
        float rden = 1.0f / (den + 1e-16f);
        float a0, a1, a2, a3;
        UNPK2(a0, a1, acc01);
        UNPK2(a2, a3, acc23);
        o0 = a0 * rden + bias[jb + 0];
        o1 = a1 * rden + bias[jb + 1];
        o2 = a2 * rden + bias[jb + 2];
        o3 = a3 * rden + bias[jb + 3];
        *(float4*)(hout + (size_t)n * DIM + jb) = make_float4(o0, o1, o2, o3);
    }
    // BN partials: per-warp disjoint smem slices, no smem atomics
    int base = wrp * DIM + jb;
    sS[base + 0] = o0;  sQ[base + 0] = o0 * o0;
    sS[base + 1] = o1;  sQ[base + 1] = o1 * o1;
    sS[base + 2] = o2;  sQ[base + 2] = o2 * o2;
    sS[base + 3] = o3;  sQ[base + 3] = o3 * o3;
    __syncthreads();
    if (tid < DIM) {
        float s = 0.f, q = 0.f;
#pragma unroll
        for (int w = 0; w < 8; w++) {
            s += sS[w * DIM + tid];
            q += sQ[w * DIM + tid];
        }
        atomicAdd(&stats[tid], s);
        atomicAdd(&stats[DIM + tid], q);
    }
}

// ---------------- BN stats finalize (and reset accumulators) ----------------
__global__ void k_bn_finalize(float* __restrict__ stats,
                              const float* __restrict__ gamma,
                              const float* __restrict__ beta,
                              float* __restrict__ bnp)
{
    int j = threadIdx.x;
    float inv_n = 1.0f / (float)N_NODES;
    float mu = stats[j] * inv_n;
    float var = stats[DIM + j] * inv_n - mu * mu;
    float rs = rsqrtf(var + 1e-5f);
    float sc = rs * gamma[j];
    bnp[j] = sc;
    bnp[DIM + j] = beta[j] - mu * sc;
    stats[j] = 0.f;
    stats[DIM + j] = 0.f;
}

// ---------------- launch ----------------
extern "C" void kernel_launch(void* const* d_in, const int* in_sizes, int n_in,
                              void* d_out, int out_size)
{
    const float* x    = (const float*)d_in[0];
    const int*   ei   = (const int*)d_in[1];     // int32
    const float* ea   = (const float*)d_in[2];
    const float* Wl   = (const float*)d_in[3];
    const float* bl   = (const float*)d_in[4];
    const float* Wr   = (const float*)d_in[5];
    const float* br   = (const float*)d_in[6];
    const float* We   = (const float*)d_in[7];
    const float* att  = (const float*)d_in[8];
    const float* bias = (const float*)d_in[9];
    const float* gamma= (const float*)d_in[10];
    const float* beta = (const float*)d_in[11];
    const float* Wf   = (const float*)d_in[12];
    const float* bf   = (const float*)d_in[13];
    float* out = (float*)d_out;

    float *p_h, *p_gl, *p_gr, *p_stats, *p_bnp;
    int *p_cnt, *p_off, *p_cur, *p_bsum;
    int2 *p_einfo;
    cudaGetSymbolAddress((void**)&p_h,     g_h);
    cudaGetSymbolAddress((void**)&p_gl,    g_gl);
    cudaGetSymbolAddress((void**)&p_gr,    g_gr);
    cudaGetSymbolAddress((void**)&p_stats, g_stats);
    cudaGetSymbolAddress((void**)&p_bnp,   g_bnp);
    cudaGetSymbolAddress((void**)&p_cnt,   g_cnt);
    cudaGetSymbolAddress((void**)&p_off,   g_off);
    cudaGetSymbolAddress((void**)&p_cur,   g_cursor);
    cudaGetSymbolAddress((void**)&p_bsum,  g_bsum);
    cudaGetSymbolAddress((void**)&p_einfo, g_einfo);

    // CSR build: 5 launches
    k_zero<<<(N_NODES + 255) / 256, 256>>>(p_cnt, p_stats);
    k_hist<<<(N_EDGES + 255) / 256, 256>>>(ei, p_cnt);
    k_scan1<<<NBLK, 1024>>>(p_cnt, p_off, p_bsum);
    k_scan23<<<(N_NODES + 255) / 256, 256>>>(p_off, p_bsum, p_cur);
    k_scatter<<<(N_EDGES + 255) / 256, 256>>>(ei, p_cur, p_einfo);

    int gemm_blocks = N_NODES / 16;          // 6250 (exact)
    int agg_blocks  = N_NODES / 8;           // 12500 (exact)

    for (int L = 0; L < 3; L++) {
        const float* hin = (L == 0) ? x : p_h;
        k_gemm_dual<<<gemm_blocks, 128>>>(hin, (L > 0) ? 1 : 0, p_bnp,
                                          Wl + L * DIM * DIM, bl + L * DIM,
                                          Wr + L * DIM * DIM, br + L * DIM,
                                          p_gl, p_gr);
        k_aggregate<<<agg_blocks, 256>>>(p_off, p_einfo, p_gl, p_gr,
                                         We + L * EDIM * DIM, att + L * DIM,
                                         bias + L * DIM, ea, p_h, p_stats);
        k_bn_finalize<<<1, 128>>>(p_stats, gamma + L * DIM, beta + L * DIM, p_bnp);
    }
    k_gemm_final<<<gemm_blocks, 128>>>(p_h, p_bnp, Wf, bf, out);
}